// round 3
// baseline (speedup 1.0000x reference)
#include <cuda_runtime.h>
#include <cuda_fp16.h>
#include <stdint.h>

// Problem dims
#define BATCH   512
#define INDIM   4096
#define OUTDIM  11008
#define NELEM   (OUTDIM * INDIM)        // 45,088,768

// ---------------- GEMM tiling (pass 2) ----------------
#define BM      128
#define BN      128
#define BK      64                      // 64 halves = 128B row -> SW128 atom
#define KTILES  (INDIM / BK)            // 64
#define STAGES  3
#define GTHREADS 256                    // 8 warps: 2 (m) x 4 (n), warp tile 64x32

#define XTILE_B (BM * BK * 2)           // 16384
#define WTILE_B (BN * BK * 2)           // 16384
#define STAGE_B (XTILE_B + WTILE_B)     // 32768
#define SMEM_B  (STAGES * STAGE_B)      // 98304

#define SW128(o) ((o) ^ (((o) >> 3) & 0x70))

// Device scratch (static globals are allowed; no runtime allocation)
__device__ __half g_xh[BATCH * INDIM];      // x in fp16 (4 MB)
__device__ __half g_wh[NELEM];              // dequantized W in fp16 (90 MB)

// ---------------- PTX helpers (base PTX only -- no 'a'-target features) ----------------
__device__ __forceinline__ uint32_t smem_u32(const void* p) {
    return (uint32_t)__cvta_generic_to_shared(p);
}
__device__ __forceinline__ void cp16(uint32_t dst, const void* src) {
    asm volatile("cp.async.cg.shared.global [%0], [%1], 16;" :: "r"(dst), "l"(src));
}
__device__ __forceinline__ void cp_commit() {
    asm volatile("cp.async.commit_group;" ::: "memory");
}
__device__ __forceinline__ void cp_wait1() {
    asm volatile("cp.async.wait_group 1;" ::: "memory");
}
__device__ __forceinline__ void ldsm4(uint32_t* r, uint32_t addr) {
    asm volatile("ldmatrix.sync.aligned.m8n8.x4.shared.b16 {%0,%1,%2,%3}, [%4];"
                 : "=r"(r[0]), "=r"(r[1]), "=r"(r[2]), "=r"(r[3]) : "r"(addr));
}
__device__ __forceinline__ void mma16816(float* c, const uint32_t* a,
                                         uint32_t b0, uint32_t b1) {
    asm volatile(
        "mma.sync.aligned.m16n8k16.row.col.f32.f16.f16.f32 "
        "{%0,%1,%2,%3}, {%4,%5,%6,%7}, {%8,%9}, {%0,%1,%2,%3};"
        : "+f"(c[0]), "+f"(c[1]), "+f"(c[2]), "+f"(c[3])
        : "r"(a[0]), "r"(a[1]), "r"(a[2]), "r"(a[3]), "r"(b0), "r"(b1));
}
__device__ __forceinline__ float ex2(float v) {
    float r;
    asm("ex2.approx.f32 %0, %1;" : "=f"(r) : "f"(v));
    return r;
}

// ---------------- pass 0: x fp32 -> fp16 ----------------
__global__ void xconv_kernel(const float* __restrict__ x) {
    int i = blockIdx.x * blockDim.x + threadIdx.x;   // one float4 per thread
    float4 v = reinterpret_cast<const float4*>(x)[i];
    __half2* d = reinterpret_cast<__half2*>(g_xh);
    d[2 * i]     = __floats2half2_rn(v.x, v.y);
    d[2 * i + 1] = __floats2half2_rn(v.z, v.w);
}

// ---------------- pass 1: QINS dequant -> fp16 weights ----------------
// w = sign * exp(log_min + (255 - s)/254 * (log_max - log_min))
//   = sign * 2^(fA + fB * s)   via MUFU.EX2; sign applied as fp16 sign-bit XOR.
__global__ void dequant_kernel(const int* __restrict__ stored,
                               const int* __restrict__ sign,
                               const float* __restrict__ log_min,
                               const float* __restrict__ log_max) {
    const size_t i = (size_t)blockIdx.x * blockDim.x + threadIdx.x;  // quad index
    const float lmn = *log_min;
    const float d   = *log_max - lmn;
    const float L2E = 1.44269504088896340736f;
    const float fB  = -d * (1.0f / 254.0f) * L2E;
    const float fA  = (lmn + d * (255.0f / 254.0f)) * L2E;

    int4 s = reinterpret_cast<const int4*>(stored)[i];
    int4 g = reinterpret_cast<const int4*>(sign)[i];

    uint32_t h0 = (uint32_t)__half_as_ushort(__float2half_rn(ex2(fA + fB * (float)s.x)))
                ^ (((uint32_t)g.x >> 16) & 0x8000u);
    uint32_t h1 = (uint32_t)__half_as_ushort(__float2half_rn(ex2(fA + fB * (float)s.y)))
                ^ (((uint32_t)g.y >> 16) & 0x8000u);
    uint32_t h2 = (uint32_t)__half_as_ushort(__float2half_rn(ex2(fA + fB * (float)s.z)))
                ^ (((uint32_t)g.z >> 16) & 0x8000u);
    uint32_t h3 = (uint32_t)__half_as_ushort(__float2half_rn(ex2(fA + fB * (float)s.w)))
                ^ (((uint32_t)g.w >> 16) & 0x8000u);

    uint2 p;
    p.x = h0 | (h1 << 16);
    p.y = h2 | (h3 << 16);
    reinterpret_cast<uint2*>(g_wh)[i] = p;
}

// ---------------- pass 2: fp16 GEMM (mma.sync) + epilogue ----------------
// out[m][n] = (sum_k x[m][k] * w[n][k] + bias[n]) * scale[n]
// Grid: (4 m-tiles fastest, 86 n-tiles) so the 4 CTAs sharing a W stripe run
// concurrently and dedup W reads in L2.
__global__ void __launch_bounds__(GTHREADS, 2) gemm_kernel(
    const float* __restrict__ scale,
    const float* __restrict__ bias,
    float* __restrict__ out) {
    extern __shared__ char smem[];
    const uint32_t sbase = smem_u32(smem);
    const int tid  = threadIdx.x;
    const int lane = tid & 31;
    const int w    = tid >> 5;
    const int wm   = w >> 2;          // 0..1  (64 m-rows each)
    const int wn   = w & 3;           // 0..3  (32 n-cols each)
    const int m0   = blockIdx.x * BM; // 0..3
    const int n0   = blockIdx.y * BN; // 0..85

    float acc[4][4][4];
#pragma unroll
    for (int a = 0; a < 4; a++)
#pragma unroll
        for (int b = 0; b < 4; b++)
#pragma unroll
            for (int c = 0; c < 4; c++) acc[a][b][c] = 0.0f;

    // ---- async stage loader: 16B per cp.async, SW128-swizzled smem ----
    const int chunk = tid & 7;        // 16B chunk within 128B row
    const int rbase = tid >> 3;       // 0..31

    auto load_stage = [&](int kt, int buf) {
        const int k0 = kt * BK;
        const uint32_t xb = sbase + (uint32_t)buf * STAGE_B;
        const uint32_t wb = xb + XTILE_B;
#pragma unroll
        for (int i = 0; i < 4; i++) {
            const int row = rbase + 32 * i;
            const uint32_t off = SW128((uint32_t)(row * 128 + chunk * 16));
            cp16(xb + off, &g_xh[(size_t)(m0 + row) * INDIM + k0 + chunk * 8]);
            cp16(wb + off, &g_wh[(size_t)(n0 + row) * INDIM + k0 + chunk * 8]);
        }
    };

    // ldmatrix lane address components
    const int a_row = lane & 15;                               // A: rows m..m+15
    const int a_kc  = (lane >> 4) << 3;                        // A: k halves +0/+8
    const int b_row = (lane & 7) + (((lane >> 4) & 1) << 3);   // B: n rows
    const int b_kc  = ((lane >> 3) & 1) << 3;                  // B: k halves

    // ---- prologue: fill 2 stages ----
    load_stage(0, 0); cp_commit();
    load_stage(1, 1); cp_commit();

    int buf = 0;
    for (int kt = 0; kt < KTILES; kt++) {
        cp_wait1();
        __syncthreads();

        if (kt + 2 < KTILES) load_stage(kt + 2, (kt + 2) % STAGES);
        cp_commit();   // commit every iter (possibly empty) to keep group counts uniform

        const uint32_t xb = sbase + (uint32_t)buf * STAGE_B;
        const uint32_t wb = xb + XTILE_B;

#pragma unroll
        for (int ks = 0; ks < 4; ks++) {
            uint32_t afr[4][4], bfr[2][4];
#pragma unroll
            for (int mi = 0; mi < 4; mi++) {
                const int row = wm * 64 + mi * 16 + a_row;
                const int kc  = ks * 16 + a_kc;
                ldsm4(afr[mi], xb + SW128((uint32_t)(row * 128 + kc * 2)));
            }
#pragma unroll
            for (int bj = 0; bj < 2; bj++) {
                const int row = wn * 32 + bj * 16 + b_row;
                const int kc  = ks * 16 + b_kc;
                ldsm4(bfr[bj], wb + SW128((uint32_t)(row * 128 + kc * 2)));
            }
#pragma unroll
            for (int mi = 0; mi < 4; mi++)
#pragma unroll
                for (int nj = 0; nj < 4; nj++)
                    mma16816(acc[mi][nj], afr[mi],
                             bfr[nj >> 1][(nj & 1) * 2],
                             bfr[nj >> 1][(nj & 1) * 2 + 1]);
        }
        buf = (buf + 1) % STAGES;
    }

    // ---- epilogue: (acc + bias) * scale, fp32 stores ----
    const int cbase = n0 + wn * 32 + (lane & 3) * 2;
#pragma unroll
    for (int nj = 0; nj < 4; nj++) {
        const int c = cbase + nj * 8;
        const float2 bb = *reinterpret_cast<const float2*>(&bias[c]);
        const float2 ss = *reinterpret_cast<const float2*>(&scale[c]);
#pragma unroll
        for (int mi = 0; mi < 4; mi++) {
            const int r0 = m0 + wm * 64 + mi * 16 + (lane >> 2);
            float2 o0, o1;
            o0.x = (acc[mi][nj][0] + bb.x) * ss.x;
            o0.y = (acc[mi][nj][1] + bb.y) * ss.y;
            o1.x = (acc[mi][nj][2] + bb.x) * ss.x;
            o1.y = (acc[mi][nj][3] + bb.y) * ss.y;
            *reinterpret_cast<float2*>(&out[(size_t)r0 * OUTDIM + c])       = o0;
            *reinterpret_cast<float2*>(&out[(size_t)(r0 + 8) * OUTDIM + c]) = o1;
        }
    }
}

// ---------------- harness entry ----------------
extern "C" void kernel_launch(void* const* d_in, const int* in_sizes, int n_in,
                              void* d_out, int out_size) {
    const float* x       = (const float*)d_in[0];
    const int*   stored  = (const int*)  d_in[1];
    const int*   sign    = (const int*)  d_in[2];
    const float* log_min = (const float*)d_in[3];
    const float* log_max = (const float*)d_in[4];
    const float* scale   = (const float*)d_in[5];
    const float* bias    = (const float*)d_in[6];
    float*       out     = (float*)d_out;
    (void)in_sizes; (void)n_in; (void)out_size;

    cudaFuncSetAttribute(gemm_kernel,
                         cudaFuncAttributeMaxDynamicSharedMemorySize, SMEM_B);

    // pass 0: x -> fp16  (512*4096 floats, 4 per thread)
    xconv_kernel<<<(BATCH * INDIM) / (256 * 4), 256>>>(x);

    // pass 1: dequant weights -> fp16 (4 elems per thread)
    dequant_kernel<<<NELEM / (256 * 4), 256>>>(stored, sign, log_min, log_max);

    // pass 2: GEMM + epilogue. m-tiles fastest for L2 W-sharing.
    dim3 grid(BATCH / BM, OUTDIM / BN);
    gemm_kernel<<<grid, GTHREADS, SMEM_B>>>(scale, bias, out);
}